// round 5
// baseline (speedup 1.0000x reference)
#include <cuda_runtime.h>
#include <cuda_bf16.h>

#define N_SPARSE 20
#define N_VARLEN 3
#define SEQ_LEN  50
#define VOCAB    100000
#define N_DENSE  13
#define VAR_TOT  (N_VARLEN * SEQ_LEN)   // 150

// Warp-per-row: coalesced index streaming, 32-way MLP on L2-resident table gathers.
__global__ __launch_bounds__(256) void linear_logit_kernel(
    const int*   __restrict__ sparse_ids,     // [B, 20]
    const int*   __restrict__ varlen_ids,     // [B, 3, 50]
    const float* __restrict__ dense_x,        // [B, 13]
    const float* __restrict__ sparse_tables,  // [20, 100000]
    const float* __restrict__ varlen_tables,  // [3, 100000]
    const float* __restrict__ dense_w,        // [13]
    float*       __restrict__ out,            // [B]
    int B)
{
    const int warp = (blockIdx.x * blockDim.x + threadIdx.x) >> 5;
    const int lane = threadIdx.x & 31;
    if (warp >= B) return;

    float acc = 0.0f;

    // ---- Phase 1: batch ALL index loads first (front-loaded LDGs -> high MLP) ----
    int sid = -1;
    if (lane < N_SPARSE)
        sid = __ldg(sparse_ids + (long)warp * N_SPARSE + lane);

    const int* vrow = varlen_ids + (long)warp * VAR_TOT;
    int vid[5];
    #pragma unroll
    for (int i = 0; i < 5; i++) {
        int idx = lane + i * 32;
        vid[i] = (idx < VAR_TOT) ? __ldg(vrow + idx) : 0;
    }

    float dx = 0.0f, dw = 0.0f;
    if (lane < N_DENSE) {
        dx = __ldg(dense_x + (long)warp * N_DENSE + lane);
        dw = __ldg(dense_w + lane);
    }

    // ---- Phase 2: dependent gathers (L2-resident tables) ----
    if (sid >= 0)
        acc += __ldg(sparse_tables + lane * VOCAB + sid);

    #pragma unroll
    for (int i = 0; i < 5; i++) {
        int idx = lane + i * 32;
        if (idx < VAR_TOT && vid[i] != 0) {
            int f = idx / SEQ_LEN;              // 0..2
            acc += __ldg(varlen_tables + f * VOCAB + vid[i]);
        }
    }

    acc += dx * dw;

    // ---- Phase 3: warp reduction ----
    #pragma unroll
    for (int off = 16; off; off >>= 1)
        acc += __shfl_down_sync(0xffffffffu, acc, off);

    if (lane == 0)
        out[warp] = acc;
}

extern "C" void kernel_launch(void* const* d_in, const int* in_sizes, int n_in,
                              void* d_out, int out_size)
{
    const int*   sparse_ids    = (const int*)  d_in[0];
    const int*   varlen_ids    = (const int*)  d_in[1];
    const float* dense_x       = (const float*)d_in[2];
    const float* sparse_tables = (const float*)d_in[3];
    const float* varlen_tables = (const float*)d_in[4];
    const float* dense_w       = (const float*)d_in[5];
    float*       out           = (float*)d_out;

    const int B = in_sizes[0] / N_SPARSE;   // 65536

    const int threads = 256;                // 8 warps = 8 rows per block
    const int rows_per_block = threads / 32;
    const int blocks = (B + rows_per_block - 1) / rows_per_block;

    linear_logit_kernel<<<blocks, threads>>>(
        sparse_ids, varlen_ids, dense_x,
        sparse_tables, varlen_tables, dense_w,
        out, B);
}